// round 4
// baseline (speedup 1.0000x reference)
#include <cuda_runtime.h>
#include <cstdint>

// out[b,c, patch p, a, d] = x[b,c, patch (p+c)&63, a, d] + pos[c*64 + (p+c)&63]
// B=8, C=64, H=W=512, patches 8x8 of 64x64, PN=64.
//
// Pure HBM-streaming permutation+bias at the read+write HBM ceiling.
// sm_103a 256-bit vector ld/st (v8.f32), streaming .cs (single-touch data).
// Each thread: 4 x v8 chunks (128B) at row-stride 16 in its patch column;
// src and dst strides identical, so one offset delta serves both.

#define W8      64                    // v8 (32B) chunks per image row
#define ROWSTEP (16 * W8)             // 16 rows, in v8 units
#define NTHREADS_TOTAL (8u * 64u * 8u * 16u * 64u)   // 4,194,304

struct __align__(32) f8 { float v[8]; };

__device__ __forceinline__ f8 ldcs_v8(const float* p) {
    f8 r;
    asm volatile("ld.global.cs.v8.f32 {%0,%1,%2,%3,%4,%5,%6,%7}, [%8];"
                 : "=f"(r.v[0]), "=f"(r.v[1]), "=f"(r.v[2]), "=f"(r.v[3]),
                   "=f"(r.v[4]), "=f"(r.v[5]), "=f"(r.v[6]), "=f"(r.v[7])
                 : "l"(p));
    return r;
}

__device__ __forceinline__ void stcs_v8(float* p, const f8& r) {
    asm volatile("st.global.cs.v8.f32 [%0], {%1,%2,%3,%4,%5,%6,%7,%8};"
                 :: "l"(p),
                    "f"(r.v[0]), "f"(r.v[1]), "f"(r.v[2]), "f"(r.v[3]),
                    "f"(r.v[4]), "f"(r.v[5]), "f"(r.v[6]), "f"(r.v[7])
                 : "memory");
}

__global__ __launch_bounds__(256) void crosspatch_kernel(
    const float* __restrict__ x,
    const float* __restrict__ pos,    // [64,64]
    float*       __restrict__ out)
{
    unsigned idx = blockIdx.x * 256u + threadIdx.x;

    // idx = (((bc)*8 + ph)*16 + a0)*64 + w8 ; thread covers a = a0 + {0,16,32,48}
    unsigned w8 = idx & 63u;          // v8-chunk within row
    unsigned t  = idx >> 6;
    unsigned a0 = t & 15u;
    unsigned t2 = t >> 4;
    unsigned ph = t2 & 7u;
    unsigned bc = t2 >> 3;            // b*64 + c
    unsigned c  = bc & 63u;

    unsigned pw = w8 >> 3;            // dest patch col (8 v8-chunks per patch)
    unsigned p  = (ph << 3) | pw;     // dest patch id
    unsigned sp = (p + c) & 63u;      // source patch id
    unsigned sph = sp >> 3;
    unsigned spw = sp & 7u;

    // offsets in v8 (8-float) units
    unsigned dst8 = ((bc << 9) + (ph  << 6) + a0) * 64u + w8;
    unsigned src8 = ((bc << 9) + (sph << 6) + a0) * 64u + (spw << 3) + (w8 & 7u);

    float bias = __ldg(&pos[(c << 6) + sp]);

    const float* sp0 = x   + (size_t)src8 * 8u;
    float*       dp0 = out + (size_t)dst8 * 8u;

    f8 v0 = ldcs_v8(sp0);
    f8 v1 = ldcs_v8(sp0 + 1u * ROWSTEP * 8u);
    f8 v2 = ldcs_v8(sp0 + 2u * ROWSTEP * 8u);
    f8 v3 = ldcs_v8(sp0 + 3u * ROWSTEP * 8u);

#pragma unroll
    for (int i = 0; i < 8; i++) { v0.v[i] += bias; v1.v[i] += bias;
                                  v2.v[i] += bias; v3.v[i] += bias; }

    stcs_v8(dp0,                      v0);
    stcs_v8(dp0 + 1u * ROWSTEP * 8u,  v1);
    stcs_v8(dp0 + 2u * ROWSTEP * 8u,  v2);
    stcs_v8(dp0 + 3u * ROWSTEP * 8u,  v3);
}

extern "C" void kernel_launch(void* const* d_in, const int* in_sizes, int n_in,
                              void* d_out, int out_size)
{
    const float* x   = (const float*)d_in[0];
    const float* pos = (const float*)d_in[1];
    float* out = (float*)d_out;

    unsigned blocks = NTHREADS_TOTAL / 256u;   // 16384
    crosspatch_kernel<<<blocks, 256>>>(x, pos, out);
}